// round 2
// baseline (speedup 1.0000x reference)
#include <cuda_runtime.h>
#include <stdint.h>
#include <math.h>

#define D        27
#define QB       512     // query batch
#define NCLS     11
#define KNN      3
#define NBLK     444     // main-kernel blocks (148 SMs * 3)
#define TILE     128     // train points staged per smem tile
#define MTHREADS 128     // main kernel threads (4 queries/thread)
#define QPT      4

typedef unsigned long long ull;

// ---------------- static device scratch (no allocations allowed) ----------
__device__ unsigned int g_scale_bits[D];
__device__ float        g_inv[D];
__device__ float        g_qm[QB * D];   // -2 * scaled query, [QB][D]
__device__ float        g_qn[QB];       // ||q_s||^2 per query
__device__ float2       g_part[(size_t)QB * NBLK * KNN]; // {d2', idx-bits}

// ---------------- f32x2 helpers -------------------------------------------
__device__ __forceinline__ ull pack2(float a, float b) {
    ull r;
    asm("mov.b64 %0, {%1, %2};"
        : "=l"(r) : "r"(__float_as_uint(a)), "r"(__float_as_uint(b)));
    return r;
}
__device__ __forceinline__ void unpack2(ull v, float& a, float& b) {
    unsigned int x, y;
    asm("mov.b64 {%0, %1}, %2;" : "=r"(x), "=r"(y) : "l"(v));
    a = __uint_as_float(x);
    b = __uint_as_float(y);
}
__device__ __forceinline__ void fma2(ull& acc, ull a, ull b) {
    asm("fma.rn.f32x2 %0, %1, %2, %0;" : "+l"(acc) : "l"(a), "l"(b));
}

// ---------------- kernel 1: zero the scale accumulators -------------------
__global__ void k_init() {
    if (threadIdx.x < D) g_scale_bits[threadIdx.x] = 0u;
}

// ---------------- kernel 2: per-column max|x| over train ------------------
// blockDim.x = 216 (= 8*27) so each thread's column index is loop-invariant
// and global loads stay fully coalesced.
__global__ void k_scale(const float* __restrict__ tf, int n) {
    __shared__ unsigned int sm[D];
    if (threadIdx.x < D) sm[threadIdx.x] = 0u;
    __syncthreads();
    int i = blockIdx.x * blockDim.x + threadIdx.x;
    int col = i % D;
    int stride = gridDim.x * blockDim.x;   // multiple of 27
    float m = 0.f;
    for (; i < n; i += stride) m = fmaxf(m, fabsf(tf[i]));
    atomicMax(&sm[col], __float_as_uint(m));   // m >= 0 -> uint order == float order
    __syncthreads();
    if (threadIdx.x < D) atomicMax(&g_scale_bits[threadIdx.x], sm[threadIdx.x]);
}

// ---------------- kernel 3: inv scale + scaled queries --------------------
__global__ void k_query(const float* __restrict__ q) {
    __shared__ float inv[D];
    int t = threadIdx.x;
    if (t < D) {
        float s = __uint_as_float(g_scale_bits[t]);
        float v = (s != 0.f) ? (1.f / s) : 0.f;   // divide_no_nan
        inv[t] = v;
        g_inv[t] = v;
    }
    __syncthreads();
    // one query per thread (blockDim == QB)
    float qn = 0.f;
    #pragma unroll
    for (int d = 0; d < D; ++d) {
        float v = q[t * D + d] * inv[d];
        qn = fmaf(v, v, qn);
        g_qm[t * D + d] = -2.f * v;
    }
    g_qn[t] = qn;
}

// ---------------- kernel 4: main distance + per-block top-3 ---------------
// Train tile is staged in smem as DUPLICATED float2 pairs {v,v} so that one
// broadcast LDS.128 yields two ready f32x2 operands in aligned register
// pairs — no pack MOVs on the FFMA2 dependency path. Point layout: 28
// pairs = d0..d26 duplicated + {xn,xn}; point stride 224 B (16B-aligned).
__global__ void __launch_bounds__(MTHREADS, 3)
k_main(const float* __restrict__ tf, int N) {
    __shared__ float2 s_tile[TILE * 28];
    __shared__ float  s_inv[D];
    const int tid = threadIdx.x;
    const int bid = blockIdx.x;
    if (tid < D) s_inv[tid] = g_inv[tid];

    // register-resident packed queries: thread owns q = tid, tid+128, tid+256, tid+384
    ull q01[D], q23[D];
    #pragma unroll
    for (int d = 0; d < D; ++d) {
        float a = g_qm[(tid          ) * D + d];
        float b = g_qm[(tid + 128    ) * D + d];
        float c = g_qm[(tid + 256    ) * D + d];
        float e = g_qm[(tid + 384    ) * D + d];
        q01[d] = pack2(a, b);
        q23[d] = pack2(c, e);
    }

    const float INF = __int_as_float(0x7f800000);
    float t0[QPT], t1[QPT], t2[QPT];
    int   i0[QPT], i1[QPT], i2[QPT];
    #pragma unroll
    for (int k = 0; k < QPT; ++k) {
        t0[k] = t1[k] = t2[k] = INF;
        i0[k] = i1[k] = i2[k] = 0;
    }

    const int chunk = (N + NBLK - 1) / NBLK;
    const int base  = bid * chunk;
    const int end   = (base + chunk < N) ? (base + chunk) : N;

    for (int pt = base; pt < end; pt += TILE) {
        const int tn = (end - pt < TILE) ? (end - pt) : TILE;
        __syncthreads();   // protect s_tile reuse (also orders s_inv on iter 0)
        // stage + scale the train tile, duplicated (coalesced global reads)
        for (int f = tid; f < tn * D; f += MTHREADS) {
            int i = f / D;
            int d = f - i * D;
            float v = tf[(pt + i) * D + d] * s_inv[d];
            s_tile[i * 28 + d] = make_float2(v, v);
        }
        __syncthreads();
        // per-point squared norm xn (stored duplicated at slot 27)
        for (int i = tid; i < tn; i += MTHREADS) {
            float s = 0.f;
            #pragma unroll
            for (int d = 0; d < D; ++d) {
                float v = s_tile[i * 28 + d].x;
                s = fmaf(v, v, s);
            }
            s_tile[i * 28 + 27] = make_float2(s, s);
        }
        __syncthreads();

        // process: d2' = xn - 2 * q.x  (qn added at the end; ordering-invariant)
        for (int i = 0; i < tn; ++i) {
            const ulonglong2* xq = (const ulonglong2*)(s_tile + i * 28); // 14 LDS.128
            // last vector = {x26 pair, xn pair}: acc init comes free
            ulonglong2 vl = xq[13];
            ull a01 = vl.y;
            ull a23 = vl.y;
            fma2(a01, vl.x, q01[26]);
            fma2(a23, vl.x, q23[26]);
            #pragma unroll
            for (int j = 0; j < 13; ++j) {
                ulonglong2 v = xq[j];
                fma2(a01, v.x, q01[2 * j]);
                fma2(a23, v.x, q23[2 * j]);
                fma2(a01, v.y, q01[2 * j + 1]);
                fma2(a23, v.y, q23[2 * j + 1]);
            }
            float d2[QPT];
            unpack2(a01, d2[0], d2[1]);
            unpack2(a23, d2[2], d2[3]);
            const int idx = pt + i;
            #pragma unroll
            for (int k = 0; k < QPT; ++k) {
                float v = d2[k];
                if (v < t2[k]) {
                    if (v < t1[k]) {
                        t2[k] = t1[k]; i2[k] = i1[k];
                        if (v < t0[k]) { t1[k] = t0[k]; i1[k] = i0[k]; t0[k] = v; i0[k] = idx; }
                        else           { t1[k] = v;     i1[k] = idx; }
                    } else { t2[k] = v; i2[k] = idx; }
                }
            }
        }
    }

    // per-thread top-3 IS the per-(query,block) top-3 — write directly
    #pragma unroll
    for (int k = 0; k < QPT; ++k) {
        int q = tid + k * MTHREADS;
        float2* o = g_part + ((size_t)q * NBLK + bid) * KNN;
        o[0] = make_float2(t0[k], __int_as_float(i0[k]));
        o[1] = make_float2(t1[k], __int_as_float(i1[k]));
        o[2] = make_float2(t2[k], __int_as_float(i2[k]));
    }
}

// ---------------- top-3 merge helper (tie-break on lower index) -----------
__device__ __forceinline__ void ins3(float v, int ix,
                                     float& r0, int& y0,
                                     float& r1, int& y1,
                                     float& r2, int& y2) {
    if (v < r2 || (v == r2 && ix < y2)) {
        if (v < r1 || (v == r1 && ix < y1)) {
            r2 = r1; y2 = y1;
            if (v < r0 || (v == r0 && ix < y0)) { r1 = r0; y1 = y0; r0 = v; y0 = ix; }
            else                                 { r1 = v;  y1 = ix; }
        } else { r2 = v; y2 = ix; }
    }
}

// ---------------- kernel 5: merge partials, kd + vote ---------------------
__global__ void k_reduce(const float* __restrict__ labels, float* __restrict__ out) {
    const int q    = blockIdx.x;
    const int tid  = threadIdx.x;   // 128
    const int lane = tid & 31;
    const int wid  = tid >> 5;
    __shared__ float sd[4 * 3];
    __shared__ int   si[4 * 3];
    const float INF = __int_as_float(0x7f800000);

    float b0 = INF, b1 = INF, b2 = INF;
    int   x0 = 0,   x1 = 0,   x2 = 0;
    const float2* p = g_part + (size_t)q * NBLK * KNN;
    for (int e = tid; e < NBLK * KNN; e += 128) {
        float2 v = p[e];
        ins3(v.x, __float_as_int(v.y), b0, x0, b1, x1, b2, x2);
    }
    // warp shuffle merge
    #pragma unroll
    for (int off = 16; off > 0; off >>= 1) {
        float o0 = __shfl_down_sync(0xffffffffu, b0, off);
        float o1 = __shfl_down_sync(0xffffffffu, b1, off);
        float o2 = __shfl_down_sync(0xffffffffu, b2, off);
        int   z0 = __shfl_down_sync(0xffffffffu, x0, off);
        int   z1 = __shfl_down_sync(0xffffffffu, x1, off);
        int   z2 = __shfl_down_sync(0xffffffffu, x2, off);
        ins3(o0, z0, b0, x0, b1, x1, b2, x2);
        ins3(o1, z1, b0, x0, b1, x1, b2, x2);
        ins3(o2, z2, b0, x0, b1, x1, b2, x2);
    }
    if (lane == 0) {
        sd[wid * 3 + 0] = b0; si[wid * 3 + 0] = x0;
        sd[wid * 3 + 1] = b1; si[wid * 3 + 1] = x1;
        sd[wid * 3 + 2] = b2; si[wid * 3 + 2] = x2;
    }
    __syncthreads();

    if (tid == 0) {
        float r0 = sd[0], r1 = sd[1], r2 = sd[2];
        int   y0 = si[0], y1 = si[1], y2 = si[2];
        #pragma unroll
        for (int e = 3; e < 12; ++e) ins3(sd[e], si[e], r0, y0, r1, y1, r2, y2);

        const float qn = g_qn[q];
        const float kd0 = sqrtf(fmaxf(r0 + qn, 0.f));
        const float kd1 = sqrtf(fmaxf(r1 + qn, 0.f));
        const float kd2 = sqrtf(fmaxf(r2 + qn, 0.f));
        out[q * KNN + 0] = kd0;
        out[q * KNN + 1] = kd1;
        out[q * KNN + 2] = kd2;

        const float w0 = (kd0 == 0.f) ? 1.f : kd0;
        const float w1 = (kd1 == 0.f) ? 1.f : kd1;
        const float w2 = (kd2 == 0.f) ? 1.f : kd2;
        const float* l0 = labels + (size_t)y0 * NCLS;
        const float* l1 = labels + (size_t)y1 * NCLS;
        const float* l2 = labels + (size_t)y2 * NCLS;

        float votes[NCLS];
        #pragma unroll
        for (int c = 0; c < NCLS; ++c)
            votes[c] = l0[c] / w0 + l1[c] / w1 + l2[c] / w2;

        int am = 0; float bm = votes[0];
        #pragma unroll
        for (int c = 1; c < NCLS; ++c)
            if (votes[c] > bm) { bm = votes[c]; am = c; }

        const bool zero_hit = (kd0 == 0.f);
        float* ro = out + QB * KNN + q * NCLS;
        #pragma unroll
        for (int c = 0; c < NCLS; ++c)
            ro[c] = zero_hit ? l0[c] : ((c == am) ? 1.f : 0.f);
    }
}

// ---------------- launch ---------------------------------------------------
extern "C" void kernel_launch(void* const* d_in, const int* in_sizes, int n_in,
                              void* d_out, int out_size) {
    const float* query = (const float*)d_in[0];   // [512,27]
    const float* tf    = (const float*)d_in[1];   // [N,27]
    const float* tl    = (const float*)d_in[2];   // [N,11]
    float* out = (float*)d_out;                   // [512*3] kd ++ [512*11] result
    const int n_elems = in_sizes[1];
    const int N = n_elems / D;

    k_init  <<<1,   32 >>>();
    k_scale <<<888, 216>>>(tf, n_elems);
    k_query <<<1,   QB >>>(query);
    k_main  <<<NBLK, MTHREADS>>>(tf, N);
    k_reduce<<<QB,  128>>>(tl, out);
}

// round 4
// speedup vs baseline: 1.5776x; 1.5776x over previous
#include <cuda_runtime.h>
#include <cuda_bf16.h>
#include <stdint.h>
#include <math.h>

#define D        27
#define QB       512
#define NCLS     11
#define KNN      3
#define SLABS    148           // train slabs
#define TILE     64            // train points per tile
#define PITCH    224           // bytes per staged row (56 words; conflict-free phases)
#define SMB_B1   (64 * PITCH)  // second buffer offset
#define SMB_INV  (128 * PITCH)
#define SMEM_TOT (128 * PITCH + 128)

// ---------------- static device scratch ------------------------------------
__device__ unsigned int g_scale_bits[D];
__device__ float        g_inv[D];
__device__ float        g_qm[QB * D];   // -2 * scaled query
__device__ float        g_qn[QB];
__device__ float2       g_part[(size_t)QB * SLABS * KNN];

// ---------------- helpers ----------------------------------------------------
__device__ __forceinline__ uint32_t smem_u32(const void* p) {
    uint32_t a;
    asm("{ .reg .u64 t; cvta.to.shared.u64 t, %1; cvt.u32.u64 %0, t; }" : "=r"(a) : "l"(p));
    return a;
}
__device__ __forceinline__ void lds64(uint32_t& x, uint32_t& y, uint32_t a) {
    asm volatile("ld.shared.v2.b32 {%0,%1}, [%2];" : "=r"(x), "=r"(y) : "r"(a));
}
__device__ __forceinline__ void sts128(uint32_t a, uint32_t w0, uint32_t w1, uint32_t w2, uint32_t w3) {
    asm volatile("st.shared.v4.b32 [%0], {%1,%2,%3,%4};"
                 :: "r"(a), "r"(w0), "r"(w1), "r"(w2), "r"(w3) : "memory");
}
__device__ __forceinline__ uint32_t pk(__nv_bfloat16 a, __nv_bfloat16 b) {
    unsigned short x = *(unsigned short*)&a, y = *(unsigned short*)&b;
    return (uint32_t)x | ((uint32_t)y << 16);
}
// store 8 linear k-pair words permuted: pos 2c = w[c], pos 2c+1 = w[c+4]
#define STBLK(a, W) do { \
    sts128((a),      (W)[0], (W)[4], (W)[1], (W)[5]); \
    sts128((a) + 16, (W)[2], (W)[6], (W)[3], (W)[7]); \
} while (0)

#define MMA(d0,d1,d2,d3, A0,A1,A2,A3, B0,B1) \
    asm volatile("mma.sync.aligned.m16n8k16.row.col.f32.bf16.bf16.f32 " \
        "{%0,%1,%2,%3}, {%4,%5,%6,%7}, {%8,%9}, {%0,%1,%2,%3};" \
        : "+f"(d0), "+f"(d1), "+f"(d2), "+f"(d3) \
        : "r"(A0), "r"(A1), "r"(A2), "r"(A3), "r"(B0), "r"(B1))

#define MMA0(d0,d1,d2,d3, A0,A1,A2,A3, B0,B1) \
    asm volatile("mma.sync.aligned.m16n8k16.row.col.f32.bf16.bf16.f32 " \
        "{%0,%1,%2,%3}, {%4,%5,%6,%7}, {%8,%9}, {%10,%11,%12,%13};" \
        : "=f"(d0), "=f"(d1), "=f"(d2), "=f"(d3) \
        : "r"(A0), "r"(A1), "r"(A2), "r"(A3), "r"(B0), "r"(B1), \
          "f"(0.f), "f"(0.f), "f"(0.f), "f"(0.f))

// ---------------- small kernels ----------------------------------------------
__global__ void k_init() { if (threadIdx.x < D) g_scale_bits[threadIdx.x] = 0u; }

__global__ void k_scale(const float* __restrict__ tf, int n) {
    __shared__ unsigned int sm[D];
    if (threadIdx.x < D) sm[threadIdx.x] = 0u;
    __syncthreads();
    int i = blockIdx.x * blockDim.x + threadIdx.x;
    int col = i % D;
    int stride = gridDim.x * blockDim.x;   // multiple of 27
    float m = 0.f;
    for (; i < n; i += stride) m = fmaxf(m, fabsf(tf[i]));
    atomicMax(&sm[col], __float_as_uint(m));
    __syncthreads();
    if (threadIdx.x < D) atomicMax(&g_scale_bits[threadIdx.x], sm[threadIdx.x]);
}

__global__ void k_query(const float* __restrict__ q) {
    __shared__ float inv[D];
    int t = threadIdx.x;
    if (t < D) {
        float s = __uint_as_float(g_scale_bits[t]);
        float v = (s != 0.f) ? (1.f / s) : 0.f;
        inv[t] = v;
        g_inv[t] = v;
    }
    __syncthreads();
    float qn = 0.f;
    #pragma unroll
    for (int d = 0; d < D; ++d) {
        float v = q[t * D + d] * inv[d];
        qn = fmaf(v, v, qn);
        g_qm[t * D + d] = -2.f * v;
    }
    g_qn[t] = qn;
}

// ---------------- producer: build one 64-point B tile -------------------------
// 2 threads per point: h=0 covers dims 0-15 (k-blocks s0,s2,s4), h=1 covers
// dims 16-26 + xn (k-blocks s1,s3,s5). Row layout per point: 96 bf16 over 6
// 16k-blocks, each block stored k-pair-permuted so LDS.64 yields (k, k+8) frags.
__device__ __forceinline__ void produce(const float* __restrict__ tf,
                                        const float* __restrict__ inv_s,
                                        uint32_t dst, int t, int N, int tid) {
    const int pt = tid >> 1, h = tid & 1;
    const int p  = t * TILE + pt;
    const bool valid = p < N;
    const int nd = h ? 11 : 16;
    float v[16];
    #pragma unroll
    for (int d = 0; d < 16; ++d) {
        float x = 0.f;
        if (d < nd && valid) x = __ldg(tf + (size_t)p * D + h * 16 + d) * inv_s[h * 16 + d];
        v[d] = x;
    }
    float ps = 0.f;
    #pragma unroll
    for (int d = 0; d < 16; ++d) ps = fmaf(v[d], v[d], ps);
    float xn = ps + __shfl_xor_sync(0xffffffffu, ps, 1);

    __nv_bfloat16 hb[16], lb[16];
    #pragma unroll
    for (int d = 0; d < 16; ++d) {
        hb[d] = __float2bfloat16(v[d]);
        lb[d] = __float2bfloat16(v[d] - __bfloat162float(hb[d]));
    }
    const uint32_t rowa = dst + pt * PITCH;
    const __nv_bfloat16 zr = __float2bfloat16(0.f);

    if (h == 0) {
        uint32_t hw[8], lw[8];
        #pragma unroll
        for (int j = 0; j < 8; ++j) {
            hw[j] = pk(hb[2*j], hb[2*j+1]);
            lw[j] = pk(lb[2*j], lb[2*j+1]);
        }
        STBLK(rowa +   0, hw);   // s0: hi  (vs A hi)
        STBLK(rowa +  64, hw);   // s2: hi  (vs A lo)
        STBLK(rowa + 128, lw);   // s4: lo  (vs A hi)
    } else {
        if (!valid) xn = 1e30f;            // padding rows excluded via huge d2
        __nv_bfloat16 xh = __float2bfloat16(xn);
        __nv_bfloat16 xl = __float2bfloat16(xn - __bfloat162float(xh));
        uint32_t b1[8], b3[8], b5[8];
        #pragma unroll
        for (int j = 0; j < 5; ++j) {
            uint32_t hp = pk(hb[2*j], hb[2*j+1]);   // dims 16..25
            b1[j] = hp; b3[j] = hp;
            b5[j] = pk(lb[2*j], lb[2*j+1]);
        }
        b1[5] = pk(hb[10], xh); b1[6] = pk(xl, zr); b1[7] = 0;  // k26=hi26, k27=xn_hi, k28=xn_lo
        b3[5] = pk(hb[10], zr); b3[6] = 0;          b3[7] = 0;
        b5[5] = pk(lb[10], zr); b5[6] = 0;          b5[7] = 0;
        STBLK(rowa +  32, b1);   // s1
        STBLK(rowa +  96, b3);   // s3
        STBLK(rowa + 160, b5);   // s5
    }
}

// ---------------- main HMMA kernel --------------------------------------------
__global__ void __launch_bounds__(128, 4)
k_hmma(const float* __restrict__ tf, int N) {
    extern __shared__ char smraw[];
    const uint32_t smb = smem_u32(smraw);
    const int tid  = threadIdx.x;
    const int w    = tid >> 5;
    const int lane = tid & 31;
    const int g    = lane >> 2;          // row-in-8 group
    const int c    = lane & 3;           // k/col group
    const int qg   = blockIdx.x & 3;
    const int slab = blockIdx.x >> 2;
    const int qbase = qg * 128;
    const int nt = (N + TILE - 1) / TILE;
    const float* inv_s = (const float*)(smraw + SMB_INV);

    if (tid < D) ((float*)(smraw + SMB_INV))[tid] = g_inv[tid];

    // ---- stage A rows (temporarily uses the whole B region: 128 rows x 224B)
    {
        const int row = tid;
        const int q = qbase + row;
        __nv_bfloat16 hi_[27], lo_[27];
        #pragma unroll
        for (int d = 0; d < 27; ++d) {
            float v = g_qm[q * 27 + d];
            __nv_bfloat16 h = __float2bfloat16(v);
            hi_[d] = h;
            lo_[d] = __float2bfloat16(v - __bfloat162float(h));
        }
        const __nv_bfloat16 one = __float2bfloat16(1.f);
        const __nv_bfloat16 zr  = __float2bfloat16(0.f);
        uint32_t hw[8], lw[8], b1[8], b3[8], b5[8];
        #pragma unroll
        for (int j = 0; j < 8; ++j) {
            hw[j] = pk(hi_[2*j], hi_[2*j+1]);
            lw[j] = pk(lo_[2*j], lo_[2*j+1]);
        }
        #pragma unroll
        for (int j = 0; j < 5; ++j) {
            b1[j] = pk(hi_[16+2*j], hi_[17+2*j]);
            b5[j] = b1[j];
            b3[j] = pk(lo_[16+2*j], lo_[17+2*j]);
        }
        b1[5] = pk(hi_[26], one); b1[6] = pk(one, zr); b1[7] = 0;  // ones at k27,k28
        b3[5] = pk(lo_[26], zr);  b3[6] = 0;           b3[7] = 0;
        b5[5] = pk(hi_[26], zr);  b5[6] = 0;           b5[7] = 0;
        const uint32_t rowa = smb + row * PITCH;
        STBLK(rowa +   0, hw);   // s0: hi_q
        STBLK(rowa +  32, b1);   // s1: hi_q tail + ones
        STBLK(rowa +  64, lw);   // s2: lo_q
        STBLK(rowa +  96, b3);   // s3: lo_q tail
        STBLK(rowa + 128, hw);   // s4: hi_q
        STBLK(rowa + 160, b5);   // s5: hi_q tail
    }
    __syncthreads();

    // ---- load A fragments into registers (persist for whole kernel)
    uint32_t a0[2][6], a1[2][6], a2[2][6], a3[2][6];
    #pragma unroll
    for (int mt = 0; mt < 2; ++mt)
        #pragma unroll
        for (int s = 0; s < 6; ++s) {
            uint32_t base = smb + (uint32_t)(w * 32 + mt * 16 + g) * PITCH + s * 32 + c * 8;
            lds64(a0[mt][s], a2[mt][s], base);
            lds64(a1[mt][s], a3[mt][s], base + 8 * PITCH);
        }
    __syncthreads();

    const float INF = __int_as_float(0x7f800000);
    float t0[4], t1[4], t2[4];
    int   i0[4], i1[4], i2[4];
    #pragma unroll
    for (int s = 0; s < 4; ++s) { t0[s]=t1[s]=t2[s]=INF; i0[s]=i1[s]=i2[s]=0; }

    #define INS(v_, idx_, s_) do { \
        float _v = (v_); \
        if (_v < t2[s_]) { \
            int _ix = (idx_); \
            if (_v < t1[s_]) { \
                t2[s_] = t1[s_]; i2[s_] = i1[s_]; \
                if (_v < t0[s_]) { t1[s_]=t0[s_]; i1[s_]=i0[s_]; t0[s_]=_v; i0[s_]=_ix; } \
                else             { t1[s_]=_v; i1[s_]=_ix; } \
            } else { t2[s_] = _v; i2[s_] = _ix; } \
        } } while (0)

    // ---- prologue: produce first tile into buffer 0
    if (slab < nt) produce(tf, inv_s, smb, slab, N, tid);
    __syncthreads();

    int it = 0;
    for (int t = slab; t < nt; t += SLABS, ++it) {
        const int buf = it & 1;
        const uint32_t bufb = smb + (uint32_t)buf * SMB_B1;
        const int tn = t + SLABS;
        if (tn < nt) produce(tf, inv_s, smb + (uint32_t)(buf ^ 1) * SMB_B1, tn, N, tid);

        // consume tile t
        #pragma unroll 2
        for (int j = 0; j < 8; ++j) {
            const uint32_t bb = bufb + (uint32_t)(j * 8 + g) * PITCH + c * 8;
            float d00,d01,d02,d03, d10,d11,d12,d13;
            uint32_t b0_, b1_;
            lds64(b0_, b1_, bb);
            MMA0(d00,d01,d02,d03, a0[0][0],a1[0][0],a2[0][0],a3[0][0], b0_,b1_);
            MMA0(d10,d11,d12,d13, a0[1][0],a1[1][0],a2[1][0],a3[1][0], b0_,b1_);
            #pragma unroll
            for (int s = 1; s < 6; ++s) {
                lds64(b0_, b1_, bb + s * 32);
                MMA(d00,d01,d02,d03, a0[0][s],a1[0][s],a2[0][s],a3[0][s], b0_,b1_);
                MMA(d10,d11,d12,d13, a0[1][s],a1[1][s],a2[1][s],a3[1][s], b0_,b1_);
            }
            const int idx0 = t * TILE + j * 8 + 2 * c;
            INS(d00, idx0,     0); INS(d01, idx0 + 1, 0);
            INS(d02, idx0,     1); INS(d03, idx0 + 1, 1);
            INS(d10, idx0,     2); INS(d11, idx0 + 1, 2);
            INS(d12, idx0,     3); INS(d13, idx0 + 1, 3);
        }
        __syncthreads();
    }

    // ---- merge top-3 across the 4 lanes of each quad (same queries, disjoint cols)
    #pragma unroll
    for (int s = 0; s < 4; ++s) {
        #pragma unroll
        for (int off = 2; off > 0; off >>= 1) {
            float o0 = __shfl_down_sync(0xffffffffu, t0[s], off);
            float o1 = __shfl_down_sync(0xffffffffu, t1[s], off);
            float o2 = __shfl_down_sync(0xffffffffu, t2[s], off);
            int   z0 = __shfl_down_sync(0xffffffffu, i0[s], off);
            int   z1 = __shfl_down_sync(0xffffffffu, i1[s], off);
            int   z2 = __shfl_down_sync(0xffffffffu, i2[s], off);
            // insert with index tie-break (lower index wins on equal distance)
            #define MINS(vv, zz) do { \
                float _v = (vv); int _z = (zz); \
                if (_v < t2[s] || (_v == t2[s] && _z < i2[s])) { \
                    if (_v < t1[s] || (_v == t1[s] && _z < i1[s])) { \
                        t2[s]=t1[s]; i2[s]=i1[s]; \
                        if (_v < t0[s] || (_v == t0[s] && _z < i0[s])) { t1[s]=t0[s]; i1[s]=i0[s]; t0[s]=_v; i0[s]=_z; } \
                        else { t1[s]=_v; i1[s]=_z; } \
                    } else { t2[s]=_v; i2[s]=_z; } \
                } } while (0)
            MINS(o0, z0); MINS(o1, z1); MINS(o2, z2);
            #undef MINS
        }
    }
    if ((lane & 3) == 0) {
        #pragma unroll
        for (int s = 0; s < 4; ++s) {
            const int q = qbase + w * 32 + (s >> 1) * 16 + g + (s & 1) * 8;
            float2* o = g_part + ((size_t)q * SLABS + slab) * KNN;
            o[0] = make_float2(t0[s], __int_as_float(i0[s]));
            o[1] = make_float2(t1[s], __int_as_float(i1[s]));
            o[2] = make_float2(t2[s], __int_as_float(i2[s]));
        }
    }
    #undef INS
}

// ---------------- merge + vote -------------------------------------------------
__device__ __forceinline__ void ins3(float v, int ix,
                                     float& r0, int& y0, float& r1, int& y1,
                                     float& r2, int& y2) {
    if (v < r2 || (v == r2 && ix < y2)) {
        if (v < r1 || (v == r1 && ix < y1)) {
            r2 = r1; y2 = y1;
            if (v < r0 || (v == r0 && ix < y0)) { r1 = r0; y1 = y0; r0 = v; y0 = ix; }
            else                                 { r1 = v;  y1 = ix; }
        } else { r2 = v; y2 = ix; }
    }
}

__global__ void k_reduce(const float* __restrict__ labels, float* __restrict__ out) {
    const int q    = blockIdx.x;
    const int tid  = threadIdx.x;   // 128
    const int lane = tid & 31;
    const int wid  = tid >> 5;
    __shared__ float sd[12];
    __shared__ int   si[12];
    const float INF = __int_as_float(0x7f800000);

    float b0 = INF, b1 = INF, b2 = INF;
    int   x0 = 0,   x1 = 0,   x2 = 0;
    const float2* p = g_part + (size_t)q * SLABS * KNN;
    for (int e = tid; e < SLABS * KNN; e += 128) {
        float2 v = p[e];
        ins3(v.x, __float_as_int(v.y), b0, x0, b1, x1, b2, x2);
    }
    #pragma unroll
    for (int off = 16; off > 0; off >>= 1) {
        float o0 = __shfl_down_sync(0xffffffffu, b0, off);
        float o1 = __shfl_down_sync(0xffffffffu, b1, off);
        float o2 = __shfl_down_sync(0xffffffffu, b2, off);
        int   z0 = __shfl_down_sync(0xffffffffu, x0, off);
        int   z1 = __shfl_down_sync(0xffffffffu, x1, off);
        int   z2 = __shfl_down_sync(0xffffffffu, x2, off);
        ins3(o0, z0, b0, x0, b1, x1, b2, x2);
        ins3(o1, z1, b0, x0, b1, x1, b2, x2);
        ins3(o2, z2, b0, x0, b1, x1, b2, x2);
    }
    if (lane == 0) {
        sd[wid * 3 + 0] = b0; si[wid * 3 + 0] = x0;
        sd[wid * 3 + 1] = b1; si[wid * 3 + 1] = x1;
        sd[wid * 3 + 2] = b2; si[wid * 3 + 2] = x2;
    }
    __syncthreads();

    if (tid == 0) {
        float r0 = sd[0], r1 = sd[1], r2 = sd[2];
        int   y0 = si[0], y1 = si[1], y2 = si[2];
        #pragma unroll
        for (int e = 3; e < 12; ++e) ins3(sd[e], si[e], r0, y0, r1, y1, r2, y2);

        const float qn = g_qn[q];
        const float kd0 = sqrtf(fmaxf(r0 + qn, 0.f));
        const float kd1 = sqrtf(fmaxf(r1 + qn, 0.f));
        const float kd2 = sqrtf(fmaxf(r2 + qn, 0.f));
        out[q * KNN + 0] = kd0;
        out[q * KNN + 1] = kd1;
        out[q * KNN + 2] = kd2;

        const float w0 = (kd0 == 0.f) ? 1.f : kd0;
        const float w1 = (kd1 == 0.f) ? 1.f : kd1;
        const float w2 = (kd2 == 0.f) ? 1.f : kd2;
        const float* l0 = labels + (size_t)y0 * NCLS;
        const float* l1 = labels + (size_t)y1 * NCLS;
        const float* l2 = labels + (size_t)y2 * NCLS;

        float votes[NCLS];
        #pragma unroll
        for (int cc = 0; cc < NCLS; ++cc)
            votes[cc] = l0[cc] / w0 + l1[cc] / w1 + l2[cc] / w2;

        int am = 0; float bm = votes[0];
        #pragma unroll
        for (int cc = 1; cc < NCLS; ++cc)
            if (votes[cc] > bm) { bm = votes[cc]; am = cc; }

        const bool zero_hit = (kd0 == 0.f);
        float* ro = out + QB * KNN + q * NCLS;
        #pragma unroll
        for (int cc = 0; cc < NCLS; ++cc)
            ro[cc] = zero_hit ? l0[cc] : ((cc == am) ? 1.f : 0.f);
    }
}

// ---------------- launch --------------------------------------------------------
extern "C" void kernel_launch(void* const* d_in, const int* in_sizes, int n_in,
                              void* d_out, int out_size) {
    const float* query = (const float*)d_in[0];
    const float* tf    = (const float*)d_in[1];
    const float* tl    = (const float*)d_in[2];
    float* out = (float*)d_out;
    const int n_elems = in_sizes[1];
    const int N = n_elems / D;

    k_init  <<<1,   32 >>>();
    k_scale <<<888, 216>>>(tf, n_elems);
    k_query <<<1,   QB >>>(query);
    k_hmma  <<<SLABS * 4, 128, SMEM_TOT>>>(tf, N);
    k_reduce<<<QB,  128>>>(tl, out);
}